// round 2
// baseline (speedup 1.0000x reference)
#include <cuda_runtime.h>
#include <cstdint>

#define B  8
#define L  30
#define D  512
#define NS 21
#define NI 8

// ---------------- scratch (device globals; no allocation) ----------------
__device__ float g_wc[B*L*NS];        // wc[b,l,s]
__device__ float g_aw[B*L];           // a_words[b,l]
__device__ float g_wsum[B*NS];        // weighted_c[b,s]
__device__ float g_aslots[B*NS];      // a_slots[b,s]
__device__ float g_aslots_sum[B];
__device__ float g_part[L*B*NS*D];    // partial u accumulators per l  (10.3 MB)
__device__ float g_uslots[B*NS*D];    // u_slots[b,s,k]
__device__ float g_wc2[B*NS*NI];      // wc2[b,s,i]
__device__ float g_wc2sum[B*NI];      // weighted_c2[b,i]
__device__ int   g_maxidx[B];
__device__ float g_part2[NS*B*D];     // partial intent accumulators per s

// ---------------- f32x2 packed-FMA helpers (sm_103a) ----------------
#define PACK2(o, a, b) asm("mov.b64 %0, {%1, %2};" : "=l"(o) : "f"(a), "f"(b))
#define UNPACK2(a, b, i) asm("mov.b64 {%0, %1}, %2;" : "=f"(a), "=f"(b) : "l"(i))
#define FMA2(acc, a, b) asm("fma.rn.f32x2 %0, %1, %2, %3;" : "=l"(acc) : "l"(a), "l"(b), "l"(acc))

// ============ Kernel A: word->slot routing (logits, softmax, wc, slots) ============
__global__ void kA(const float* __restrict__ x, const float* __restrict__ wr,
                   float* __restrict__ out) {
    int b = blockIdx.x / L, l = blockIdx.x % L;
    __shared__ float xs[D];
    __shared__ float logits[NS];
    __shared__ float red[4];
    const float* xp = x + (size_t)(b*L + l)*D;
    int tid = threadIdx.x;              // 128 threads
    float psum = 0.f;
    for (int j = tid; j < D; j += 128) { float v = xp[j]; xs[j] = v; psum += v; }
    for (int o = 16; o; o >>= 1) psum += __shfl_xor_sync(~0u, psum, o);
    if ((tid & 31) == 0) red[tid >> 5] = psum;
    __syncthreads();
    float aw = (red[0] + red[1] + red[2] + red[3]) * (1.f / (float)D);
    int w = tid >> 5, lane = tid & 31;
    for (int n = w; n < NS; n += 4) {
        const float* wrow = wr + (size_t)(l*NS + n)*D;
        float acc = 0.f;
        for (int j = lane; j < D; j += 32) acc += wrow[j] * xs[j];
        for (int o = 16; o; o >>= 1) acc += __shfl_xor_sync(~0u, acc, o);
        if (lane == 0) logits[n] = acc;
    }
    __syncthreads();
    if (tid == 0) {
        float mx = logits[0]; int am = 0;
        for (int n = 1; n < NS; n++) if (logits[n] > mx) { mx = logits[n]; am = n; }
        float e[NS], se = 0.f;
        for (int n = 0; n < NS; n++) { e[n] = expf(logits[n] - mx); se += e[n]; }
        float inv = aw / se;
        for (int n = 0; n < NS; n++) g_wc[(b*L + l)*NS + n] = e[n] * inv;
        g_aw[b*L + l] = aw;
        out[b*L + l] = (float)am;   // slots (argmax of logits == argmax of softmax)
    }
}

// ============ Kernel B: per-batch slot statistics ============
__global__ void kB() {
    int b = blockIdx.x, lane = threadIdx.x;   // 32 threads
    float wsum = 0.f;
    if (lane < NS) for (int l = 0; l < L; l++) wsum += g_wc[(b*L + l)*NS + lane];
    float awp = 0.f;
    for (int l = lane; l < L; l += 32) awp += g_aw[b*L + l];
    for (int o = 16; o; o >>= 1) awp += __shfl_xor_sync(~0u, awp, o);
    float asl = (lane < NS) ? wsum / awp : 0.f;
    float ssum = asl;
    for (int o = 16; o; o >>= 1) ssum += __shfl_xor_sync(~0u, ssum, o);
    if (lane < NS) { g_wsum[b*NS + lane] = wsum; g_aslots[b*NS + lane] = asl; }
    if (lane == 0) g_aslots_sum[b] = ssum;
}

// ============ Kernel C: pose stream — THE heavy kernel (660 MB weight read) ============
// u_hat_slots[b,l,s,i] = sum_j W[l,s,i,j] * x[b,l,j]  (true contraction)
// block = one (s,l) pair; emits wc-weighted partials to g_part[l][b,s,k].
__global__ __launch_bounds__(512, 1) void kC(const float* __restrict__ x,
                                             const float* __restrict__ wp) {
    int blk = blockIdx.x;
    int s = blk / L, l = blk % L;
    __shared__ float4 xs4[B*(D/4)];          // x[b][j], 16 KB
    __shared__ float  wcs[B];
    int tid = threadIdx.x;
    for (int i = tid; i < B*(D/4); i += 512) {
        int b = i >> 7, j4 = i & 127;
        xs4[i] = ((const float4*)(x + (size_t)(b*L + l)*D))[j4];
    }
    if (tid < B) wcs[tid] = g_wc[(tid*L + l)*NS + s];
    __syncthreads();
    int w = tid >> 5, lane = tid & 31;
    const float* Wp = wp + (size_t)(l*NS + s)*D*D;
    float* partp = g_part + (size_t)l*(B*NS*D);
    const int rr = lane >> 3, bb = lane & 7;
    for (int rg = 0; rg < 8; rg++) {
        int k0 = (w << 5) + (rg << 2);
        unsigned long long acc[4][8];
        #pragma unroll
        for (int r = 0; r < 4; r++)
            #pragma unroll
            for (int b = 0; b < 8; b++) acc[r][b] = 0ull;
        #pragma unroll
        for (int jj = 0; jj < 4; jj++) {
            int idx = (jj << 5) + lane;
            float4 wv[4];
            unsigned long long wpk[4][2];
            #pragma unroll
            for (int r = 0; r < 4; r++) {
                wv[r] = ((const float4*)(Wp + (size_t)(k0 + r)*D))[idx];
                PACK2(wpk[r][0], wv[r].x, wv[r].y);
                PACK2(wpk[r][1], wv[r].z, wv[r].w);
            }
            #pragma unroll
            for (int b = 0; b < 8; b++) {
                float4 xv = xs4[(b << 7) + idx];
                unsigned long long x01, x23;
                PACK2(x01, xv.x, xv.y);
                PACK2(x23, xv.z, xv.w);
                #pragma unroll
                for (int r = 0; r < 4; r++) {
                    FMA2(acc[r][b], wpk[r][0], x01);
                    FMA2(acc[r][b], wpk[r][1], x23);
                }
            }
        }
        float myv = 0.f;
        #pragma unroll
        for (int r = 0; r < 4; r++)
            #pragma unroll
            for (int b = 0; b < 8; b++) {
                float lo, hi; UNPACK2(lo, hi, acc[r][b]);
                float v = lo + hi;
                for (int o = 16; o; o >>= 1) v += __shfl_xor_sync(~0u, v, o);
                if (rr == r && bb == b) myv = v;
            }
        partp[((bb*NS + s) << 9) + k0 + rr] = myv * wcs[bb];
    }
}

// ============ Kernel D: fixed-order reduce over l -> u_slots ============
__global__ void kD() {
    int t = blockIdx.x * 256 + threadIdx.x;       // [0, B*NS*D)
    float sum = 0.f;
    for (int l = 0; l < L; l++) sum += g_part[(size_t)l*(B*NS*D) + t];
    int bs = t >> 9;
    g_uslots[t] = sum / g_wsum[bs];
}

// ============ Kernel E: slot->intent routing, a_intents, argmax dispatch ============
__global__ void kE(const float* __restrict__ wr_si) {
    int b = blockIdx.x, tid = threadIdx.x;        // 256 threads
    int w = tid >> 5, lane = tid & 31;
    __shared__ float lg[NS*NI];
    for (int d = w; d < NS*NI; d += 8) {
        int s = d / NI, i = d % NI;
        const float* wr = wr_si + (size_t)(s*NI + i)*D;
        const float* u = g_uslots + (size_t)(b*NS + s)*D;
        float acc = 0.f;
        for (int j = lane; j < D; j += 32) acc += wr[j] * u[j];
        for (int o = 16; o; o >>= 1) acc += __shfl_xor_sync(~0u, acc, o);
        if (lane == 0) lg[d] = acc;
    }
    __syncthreads();
    if (tid < 8) {
        int i = tid;
        float wcsum = 0.f;
        for (int s = 0; s < NS; s++) {
            float v = lg[s*NI + i];
            float m = v;
            for (int o = 4; o; o >>= 1) m = fmaxf(m, __shfl_xor_sync(0xff, m, o));
            float e = expf(v - m);
            float se = e;
            for (int o = 4; o; o >>= 1) se += __shfl_xor_sync(0xff, se, o);
            float wc2 = (e / se) * g_aslots[b*NS + s];
            g_wc2[(b*NS + s)*NI + i] = wc2;
            wcsum += wc2;
        }
        g_wc2sum[b*NI + i] = wcsum;
        lg[i] = wcsum / g_aslots_sum[b];          // a_intents
    }
    __syncthreads();
    if (tid == 0) {
        float mx = lg[0]; int am = 0;
        for (int i = 1; i < NI; i++) if (lg[i] > mx) { mx = lg[i]; am = i; }
        g_maxidx[b] = am;
    }
}

// ============ Kernel F: selected-intent COLUMN-SUM stream ============
// Reference einsum 'sijk,bsk->bsik' sums over j (only in weights!):
//   u_hat_intents[b,s,i,k] = (sum_j W[s,i,j,k]) * u_slots[b,s,k]
// So per (b,s): stream W[s,ii] (1 MB), column-reduce over j, elementwise * u.
__global__ __launch_bounds__(512, 1) void kF(const float* __restrict__ wps) {
    int blk = blockIdx.x;
    int b = blk / NS, s = blk % NS;
    int ii = g_maxidx[b];
    int k = threadIdx.x;                           // 512 threads == D columns
    const float* Wp = wps + (size_t)(s*NI + ii)*D*D + k;
    float acc = 0.f;
    #pragma unroll 8
    for (int j = 0; j < D; j++) acc += Wp[(size_t)j*D];
    float u = g_uslots[(size_t)(b*NS + s)*D + k];
    float wc2s = g_wc2[(b*NS + s)*NI + ii];
    g_part2[(size_t)s*(B*D) + (b << 9) + k] = acc * u * wc2s;
}

// ============ Kernel G: fixed-order reduce over s + cls residual -> intents ============
__global__ void kG(const float* __restrict__ cls, float* __restrict__ out) {
    int t = blockIdx.x * 256 + threadIdx.x;       // [0, B*D)
    int b = t >> 9;
    float sum = 0.f;
    for (int s = 0; s < NS; s++) sum += g_part2[(size_t)s*(B*D) + t];
    int ii = g_maxidx[b];
    out[B*L + t] = cls[t] + sum / g_wc2sum[b*NI + ii];
}

// ---------------- launch ----------------
extern "C" void kernel_launch(void* const* d_in, const int* in_sizes, int n_in,
                              void* d_out, int out_size) {
    const float* x     = (const float*)d_in[0];  // token_features (B,L,D)
    const float* cls   = (const float*)d_in[1];  // cls_token (B,D)
    const float* w_rws = (const float*)d_in[2];  // w_route_ws (L,NS,D)
    const float* w_pws = (const float*)d_in[3];  // w_pose_ws (L,NS,D,D)
    const float* w_rsi = (const float*)d_in[4];  // w_route_si (NS,NI,D)
    const float* w_psi = (const float*)d_in[5];  // w_pose_si (NS,NI,D,D)
    float* out = (float*)d_out;

    kA<<<B*L, 128>>>(x, w_rws, out);
    kB<<<B, 32>>>();
    kC<<<NS*L, 512>>>(x, w_pws);
    kD<<<(B*NS*D)/256, 256>>>();
    kE<<<B, 256>>>(w_rsi);
    kF<<<B*NS, 512>>>(w_psi);
    kG<<<(B*D)/256, 256>>>(cls, out);
}